// round 8
// baseline (speedup 1.0000x reference)
#include <cuda_runtime.h>
#include <cuda_bf16.h>
#include <cstdint>

typedef unsigned long long ull;

// ---------------- scratch (device globals: allocation-free) ----------------
__device__ float g_xw[(size_t)64 * 1024 * 1536];   // 402 MB input projections
__device__ float g_h0[64 * 512];
__device__ float g_h1[64 * 512];
__device__ unsigned g_ctr[8 * 32];                 // per-bg counters, 128B apart

// ---------------- f32x2 helpers ----------------
__device__ __forceinline__ void fma2(ull& d, ull a, ull b) {
    asm("fma.rn.f32x2 %0, %1, %2, %0;" : "+l"(d) : "l"(a), "l"(b));
}
__device__ __forceinline__ ull splat2(float x) {
    ull r; asm("mov.b64 %0, {%1, %1};" : "=l"(r) : "f"(x)); return r;
}
__device__ __forceinline__ ull pack2(float x, float y) {
    ull r; asm("mov.b64 %0, {%1, %2};" : "=l"(r) : "f"(x), "f"(y)); return r;
}
__device__ __forceinline__ void f4_to_u2(float4 v, ull& a, ull& b) {
    asm("mov.b64 %0, {%1, %2};" : "=l"(a) : "f"(v.x), "f"(v.y));
    asm("mov.b64 %0, {%1, %2};" : "=l"(b) : "f"(v.z), "f"(v.w));
}
__device__ __forceinline__ float2 unpk(ull v) {
    float2 r; asm("mov.b64 {%0, %1}, %2;" : "=f"(r.x), "=f"(r.y) : "l"(v)); return r;
}

__device__ __forceinline__ float sigf(float x) {
    return __fdividef(1.0f, 1.0f + __expf(-x));
}
__device__ __forceinline__ float tanh_acc(float x) {
    float ax = fabsf(x);
    float e = __expf(-2.0f * ax);
    float r = __fdividef(1.0f - e, 1.0f + e);
    return copysignf(r, x);
}

// ============================================================================
// Phase 1: xw = x @ W + b_in    (M=65536, K=512, N=1536), f32x2 SGEMM
// ============================================================================
#define P1_BM 128
#define P1_BN 256
#define P1_BK 16

__global__ void __launch_bounds__(256, 1) gemm_xw_kernel(
    const float* __restrict__ A,
    const float* __restrict__ W,
    const float* __restrict__ bias,
    float* __restrict__ C)
{
    __shared__ float As[P1_BK * (P1_BM + 4)];
    __shared__ float Bs[P1_BK * P1_BN];

    const int tid = threadIdx.x;
    const int tx = tid & 15;
    const int ty = tid >> 4;
    const int bm = blockIdx.y * P1_BM;
    const int bn = blockIdx.x * P1_BN;

    ull acc[8][8];
#pragma unroll
    for (int m = 0; m < 8; m++)
#pragma unroll
        for (int g = 0; g < 8; g++) acc[m][g] = 0ull;

    for (int kk = 0; kk < 512; kk += P1_BK) {
#pragma unroll
        for (int i = 0; i < 2; i++) {
            int s = tid + i * 256;
            int m = s >> 2;
            int kq = (s & 3) << 2;
            float4 v = *(const float4*)(A + (size_t)(bm + m) * 512 + kk + kq);
            As[(kq + 0) * (P1_BM + 4) + m] = v.x;
            As[(kq + 1) * (P1_BM + 4) + m] = v.y;
            As[(kq + 2) * (P1_BM + 4) + m] = v.z;
            As[(kq + 3) * (P1_BM + 4) + m] = v.w;
        }
#pragma unroll
        for (int i = 0; i < 4; i++) {
            int s = tid + i * 256;
            int k = s >> 6;
            int n4 = (s & 63) << 2;
            float4 v = *(const float4*)(W + (size_t)(kk + k) * 1536 + bn + n4);
            *(float4*)(Bs + k * P1_BN + n4) = v;
        }
        __syncthreads();

#pragma unroll
        for (int k = 0; k < P1_BK; k++) {
            float4 a0 = *(const float4*)(As + k * (P1_BM + 4) + ty * 8);
            float4 a1 = *(const float4*)(As + k * (P1_BM + 4) + ty * 8 + 4);
            ull bp[8];
#pragma unroll
            for (int g = 0; g < 4; g++) {
                float4 b4 = *(const float4*)(Bs + k * P1_BN + tx * 4 + 64 * g);
                f4_to_u2(b4, bp[2 * g], bp[2 * g + 1]);
            }
            float am[8] = {a0.x, a0.y, a0.z, a0.w, a1.x, a1.y, a1.z, a1.w};
#pragma unroll
            for (int m = 0; m < 8; m++) {
                ull as = splat2(am[m]);
#pragma unroll
                for (int g = 0; g < 8; g++) fma2(acc[m][g], as, bp[g]);
            }
        }
        __syncthreads();
    }

    float4 bi[4];
#pragma unroll
    for (int g = 0; g < 4; g++)
        bi[g] = *(const float4*)(bias + bn + tx * 4 + 64 * g);
#pragma unroll
    for (int m = 0; m < 8; m++) {
        float* crow = C + (size_t)(bm + ty * 8 + m) * 1536;
#pragma unroll
        for (int g = 0; g < 4; g++) {
            float2 p0 = unpk(acc[m][2 * g]);
            float2 p1 = unpk(acc[m][2 * g + 1]);
            float4 o;
            o.x = p0.x + bi[g].x; o.y = p0.y + bi[g].y;
            o.z = p1.x + bi[g].z; o.w = p1.y + bi[g].w;
            *(float4*)(crow + bn + tx * 4 + 64 * g) = o;
        }
    }
}

// ============================================================================
// Phase 2 v3: 128 CTAs (1/SM, uniform), each = TWO independent 128-thread
//   groups ("virtual CTAs") on DIFFERENT batch-groups:
//   group g handles logical half g*128+bid  ->  bgid = half>>5, ugid = half&31.
//   Co-resident pair is always bg x with bg x+4 => decorrelated stalls; while
//   one group sits in its poll/L2 window the other issues FFMA2.
//   Group-private named barriers (bar.sync 1/2, 128), h-staging, reduction,
//   counter. R in regs: 96 f32x2/thread (v1-proven budget).
//   Thread roles: GEMM warp wl = 128-k chunk, lane = (unit uu, k-half kh);
//   epilogue thread l = (batch eb, unit eu).
// ============================================================================
#define V3_NB 128

__global__ void __launch_bounds__(256, 1) gru_seq_v3(
    const float* __restrict__ xw,    // [65536, 1536]
    const float* __restrict__ rk,    // [512, 1536]
    const float* __restrict__ bias,  // [2, 1536]
    float* __restrict__ out,         // [64, 1024, 512]
    float* __restrict__ h0buf,
    float* __restrict__ h1buf,
    unsigned* __restrict__ ctr)
{
    __shared__ float hs[2][8 * 512];         // 32 KB (per-group h stage)
    __shared__ float red[2][8 * 16 * 13];    // 13 KB (pad 13, coprime 32)
    __shared__ float sbias[2][48];

    const int tid = threadIdx.x;
    const int g = tid >> 7;              // group 0/1
    const int l = tid & 127;             // tid within group
    const int half = g * 128 + blockIdx.x;   // logical half-CTA id, 0..255
    const int bgid = half >> 5;          // 0..7
    const int ugid = half & 31;          // 0..31
    const int u0 = ugid * 16;
    const int b0 = bgid * 8;
    const int barid = g + 1;             // named barrier 1 or 2

    const int wl = l >> 5;               // warp within group: 128-k chunk
    const int lane = tid & 31;
    const int uu = lane & 15;            // unit within group
    const int kh = lane >> 4;            // k-half
    const int k0 = wl * 128 + kh * 64;   // this thread's 64-k slice

    float* hsg = hs[g];
    float* redg = red[g];

    // ---- R slice into registers: unit u0+uu, k in [k0, k0+64) ----
    ull Rz[32], Rr[32], Rh[32];
    {
        const float* rbase = rk + u0 + uu;
#pragma unroll
        for (int i = 0; i < 32; i++) {
            const float* r0 = rbase + (size_t)(k0 + 2 * i) * 1536;
            const float* r1 = r0 + 1536;
            Rz[i] = pack2(r0[0],    r1[0]);
            Rr[i] = pack2(r0[512],  r1[512]);
            Rh[i] = pack2(r0[1024], r1[1024]);
        }
    }
    if (l < 48) {
        int u = l / 3, gg = l - u * 3;
        sbias[g][u * 3 + gg] = bias[1536 + gg * 512 + u0 + u];
    }
    asm volatile("bar.sync %0, 128;" :: "r"(barid) : "memory");

    // epilogue role: thread l = (batch eb, unit eu)
    const int eb = l >> 4;
    const int eu = l & 15;
    const float* xwp = xw + (size_t)(b0 + eb) * 1024 * 1536 + u0 + eu;
    float* outp = out + (size_t)(b0 + eb) * 524288 + u0 + eu;
    unsigned* myctr = ctr + bgid * 32;

    float hn_prev = 0.0f;

    for (int t = 0; t < 1024; t++) {
        // prefetch gate inputs (independent of h)
        const float* xr_ = xwp + (size_t)t * 1536;
        float xz = __ldg(xr_);
        float xr = __ldg(xr_ + 512);
        float xh = __ldg(xr_ + 1024);

        const float* hin = (t & 1) ? h1buf : h0buf;
        if (t > 0) {
            if (l == 0) {
                unsigned target = (unsigned)(32 * t);
                unsigned v;
                do {
                    asm volatile("ld.acquire.gpu.global.u32 %0, [%1];"
                                 : "=r"(v) : "l"(myctr) : "memory");
                } while (v < target);
            }
            asm volatile("bar.sync %0, 128;" :: "r"(barid) : "memory");
        }

        // ---- staging: warp wl stages k slice [wl*128, +128) for all 8 b ----
#pragma unroll
        for (int i = 0; i < 8; i++) {
            int j4 = lane & 31;           // float4 index within 128-k slice
            float4 v = __ldcg((const float4*)(hin + (b0 + i) * 512 + wl * 128) + j4);
            *(float4*)(hsg + i * 512 + wl * 128 + j4 * 4) = v;
            (void)0;
        }
        __syncwarp();

        // ---- GEMM partials: thread covers k in [k0, k0+64) ----
#pragma unroll 1
        for (int b = 0; b < 8; b++) {
            ull az = 0ull, ar = 0ull, ah = 0ull;
            const float4* hp = (const float4*)(hsg + b * 512 + k0);
#pragma unroll
            for (int q = 0; q < 16; q++) {
                float4 h4 = hp[q];
                ull h01, h23;
                f4_to_u2(h4, h01, h23);
                fma2(az, h01, Rz[2 * q]); fma2(az, h23, Rz[2 * q + 1]);
                fma2(ar, h01, Rr[2 * q]); fma2(ar, h23, Rr[2 * q + 1]);
                fma2(ah, h01, Rh[2 * q]); fma2(ah, h23, Rh[2 * q + 1]);
            }
            float2 p;
            p = unpk(az); float vz = p.x + p.y;
            p = unpk(ar); float vr = p.x + p.y;
            p = unpk(ah); float vh = p.x + p.y;
            vz += __shfl_down_sync(0xffffffffu, vz, 16);
            vr += __shfl_down_sync(0xffffffffu, vr, 16);
            vh += __shfl_down_sync(0xffffffffu, vh, 16);
            if (kh == 0) {
                float* rb = redg + (b * 16 + uu) * 13 + wl * 3;
                rb[0] = vz; rb[1] = vr; rb[2] = vh;
            }
        }
        asm volatile("bar.sync %0, 128;" :: "r"(barid) : "memory");

        // ---- gates: thread = (batch eb, unit eu) ----
        float rz = sbias[g][eu * 3 + 0];
        float rr = sbias[g][eu * 3 + 1];
        float rh = sbias[g][eu * 3 + 2];
        const float* rb = redg + (eb * 16 + eu) * 13;
#pragma unroll
        for (int s = 0; s < 4; s++) {
            rz += rb[s * 3 + 0];
            rr += rb[s * 3 + 1];
            rh += rb[s * 3 + 2];
        }
        float z  = sigf(xz + rz);
        float r  = sigf(xr + rr);
        float hh = tanh_acc(xh + r * rh);
        float hn = z * hn_prev + (1.0f - z) * hh;
        hn_prev = hn;

        float* hout = (t & 1) ? h0buf : h1buf;
        __stcg(hout + (b0 + eb) * 512 + u0 + eu, hn);
        asm volatile("bar.sync %0, 128;" :: "r"(barid) : "memory");
        if (l == 0) {
            asm volatile("fence.acq_rel.gpu;" ::: "memory");
            asm volatile("red.relaxed.gpu.global.add.u32 [%0], %1;"
                         :: "l"(myctr), "r"(1u) : "memory");
        }

        // out write off the critical path
        outp[(size_t)t * 512] = hn;
    }
}

// ============================================================================
extern "C" void kernel_launch(void* const* d_in, const int* in_sizes, int n_in,
                              void* d_out, int out_size) {
    const float* x    = (const float*)d_in[0];
    const float* W    = (const float*)d_in[1];
    const float* R    = (const float*)d_in[2];
    const float* bias = (const float*)d_in[3];
    float* out = (float*)d_out;

    float *xw_ptr, *h0_ptr, *h1_ptr;
    unsigned* ctr_ptr;
    cudaGetSymbolAddress((void**)&xw_ptr, g_xw);
    cudaGetSymbolAddress((void**)&h0_ptr, g_h0);
    cudaGetSymbolAddress((void**)&h1_ptr, g_h1);
    cudaGetSymbolAddress((void**)&ctr_ptr, g_ctr);

    cudaMemsetAsync(h0_ptr, 0, 64 * 512 * sizeof(float));
    cudaMemsetAsync(ctr_ptr, 0, 8 * 32 * sizeof(unsigned));

    dim3 g1(1536 / P1_BN, 65536 / P1_BM);
    gemm_xw_kernel<<<g1, 256>>>(x, W, bias, xw_ptr);

    gru_seq_v3<<<V3_NB, 256>>>(xw_ptr, R, bias, out, h0_ptr, h1_ptr, ctr_ptr);
}

// round 9
// speedup vs baseline: 1.2382x; 1.2382x over previous
#include <cuda_runtime.h>
#include <cuda_bf16.h>
#include <cstdint>

typedef unsigned long long ull;

// ---------------- scratch (device globals: allocation-free) ----------------
__device__ float    g_xw[(size_t)64 * 1024 * 1536];   // 402 MB xw projections
__device__ uint32_t g_xh[(size_t)64 * 1024 * 256];    // 67 MB x hi (bf16x2 pairs)
__device__ uint32_t g_xl[(size_t)64 * 1024 * 256];    // 67 MB x lo
__device__ uint32_t g_wh[1536 * 256];                 // W^T hi (bf16x2 pairs)
__device__ uint32_t g_wl[1536 * 256];                 // W^T lo
__device__ float    g_h0[64 * 512];
__device__ float    g_h1[64 * 512];
__device__ unsigned g_ctr[8 * 32];

// ---------------- f32x2 helpers ----------------
__device__ __forceinline__ void fma2(ull& d, ull a, ull b) {
    asm("fma.rn.f32x2 %0, %1, %2, %0;" : "+l"(d) : "l"(a), "l"(b));
}
__device__ __forceinline__ ull pack2(float x, float y) {
    ull r; asm("mov.b64 %0, {%1, %2};" : "=l"(r) : "f"(x), "f"(y)); return r;
}
__device__ __forceinline__ void f4_to_u2(float4 v, ull& a, ull& b) {
    asm("mov.b64 %0, {%1, %2};" : "=l"(a) : "f"(v.x), "f"(v.y));
    asm("mov.b64 %0, {%1, %2};" : "=l"(b) : "f"(v.z), "f"(v.w));
}
__device__ __forceinline__ float2 unpk(ull v) {
    float2 r; asm("mov.b64 {%0, %1}, %2;" : "=f"(r.x), "=f"(r.y) : "l"(v)); return r;
}
__device__ __forceinline__ float sigf(float x) {
    return __fdividef(1.0f, 1.0f + __expf(-x));
}
__device__ __forceinline__ float tanh_acc(float x) {
    float ax = fabsf(x);
    float e = __expf(-2.0f * ax);
    float r = __fdividef(1.0f - e, 1.0f + e);
    return copysignf(r, x);
}

// ---------------- bf16 split helpers ----------------
__device__ __forceinline__ uint32_t bf16pair(float even, float odd) {
    __nv_bfloat16 h0 = __float2bfloat16(even);
    __nv_bfloat16 h1 = __float2bfloat16(odd);
    return ((uint32_t)__bfloat16_as_ushort(h1) << 16) |
           (uint32_t)__bfloat16_as_ushort(h0);
}

// ============================================================================
// Converters: x -> packed bf16x2 hi/lo [m][256]; W -> transposed [n][256]
// ============================================================================
__global__ void conv_x_kernel(const float* __restrict__ x,
                              uint32_t* __restrict__ xh,
                              uint32_t* __restrict__ xl) {
    size_t p = (size_t)blockIdx.x * 256 + threadIdx.x;   // pair index
    float2 v = ((const float2*)x)[p];
    __nv_bfloat16 h0 = __float2bfloat16(v.x);
    __nv_bfloat16 h1 = __float2bfloat16(v.y);
    float f0 = __bfloat162float(h0), f1 = __bfloat162float(h1);
    xh[p] = ((uint32_t)__bfloat16_as_ushort(h1) << 16) |
            (uint32_t)__bfloat16_as_ushort(h0);
    xl[p] = bf16pair(v.x - f0, v.y - f1);
}

__global__ void conv_w_kernel(const float* __restrict__ W,
                              uint32_t* __restrict__ wh,
                              uint32_t* __restrict__ wl) {
    int idx = blockIdx.x * 256 + threadIdx.x;   // n*256 + kp, 393216 total
    int n = idx >> 8;
    int kp = idx & 255;
    float v0 = W[(size_t)(2 * kp) * 1536 + n];
    float v1 = W[(size_t)(2 * kp + 1) * 1536 + n];
    __nv_bfloat16 h0 = __float2bfloat16(v0);
    __nv_bfloat16 h1 = __float2bfloat16(v1);
    float f0 = __bfloat162float(h0), f1 = __bfloat162float(h1);
    wh[idx] = ((uint32_t)__bfloat16_as_ushort(h1) << 16) |
              (uint32_t)__bfloat16_as_ushort(h0);
    wl[idx] = bf16pair(v0 - f0, v1 - f1);
}

// ============================================================================
// Phase 1: xw = x @ W + b_in via bf16x3 tensor-core mma (m16n8k16).
//   128x128 tile, KT=32 (16 pairs), cp.async double buffer, 8 warps (4M x 2N),
//   warp tile 32M x 64N. Padded smem rows (20 words) -> conflict-free frags.
// ============================================================================
#define APAD 20
#define KPT 16     // k-pairs per tile

__device__ __forceinline__ void cpa16(uint32_t saddr, const void* g) {
    asm volatile("cp.async.cg.shared.global [%0], [%1], 16;"
                 :: "r"(saddr), "l"(g));
}
__device__ __forceinline__ void mma_bf16(float* c, const uint32_t* a,
                                         uint32_t b0, uint32_t b1) {
    asm volatile(
        "mma.sync.aligned.m16n8k16.row.col.f32.bf16.bf16.f32 "
        "{%0,%1,%2,%3}, {%4,%5,%6,%7}, {%8,%9}, {%0,%1,%2,%3};"
        : "+f"(c[0]), "+f"(c[1]), "+f"(c[2]), "+f"(c[3])
        : "r"(a[0]), "r"(a[1]), "r"(a[2]), "r"(a[3]), "r"(b0), "r"(b1));
}

__global__ void __launch_bounds__(256, 2) gemm_xw_bf16x3(
    const uint32_t* __restrict__ Ahg,   // [65536][256] pairs
    const uint32_t* __restrict__ Alg,
    const uint32_t* __restrict__ Bhg,   // [1536][256] pairs (W^T)
    const uint32_t* __restrict__ Blg,
    const float* __restrict__ bias,     // [2,1536], row 0
    float* __restrict__ C)              // [65536][1536]
{
    extern __shared__ uint32_t smw[];
    uint32_t* As = smw;                 // [buf][comp][128][APAD]
    uint32_t* Bs = smw + 2 * 2 * 128 * APAD;

    const int tid = threadIdx.x;
    const int lane = tid & 31;
    const int wid = tid >> 5;
    const int wm = (wid & 3) * 32;
    const int wn = (wid >> 2) * 64;
    const int bm = blockIdx.y * 128;
    const int bn = blockIdx.x * 128;

    const uint32_t as_b = (uint32_t)__cvta_generic_to_shared(As);
    const uint32_t bs_b = (uint32_t)__cvta_generic_to_shared(Bs);

    float acc[2][8][4];
#pragma unroll
    for (int mf = 0; mf < 2; mf++)
#pragma unroll
        for (int nf = 0; nf < 8; nf++)
#pragma unroll
            for (int i = 0; i < 4; i++) acc[mf][nf][i] = 0.0f;

    // per-thread load slots: 2 per comp per matrix
    const int row0 = tid >> 2, j0 = (tid & 3);
    const int row1 = (tid + 256) >> 2, j1 = ((tid + 256) & 3);

    auto load_tile = [&](int kt, int buf) {
        int kw = kt * KPT;
#pragma unroll
        for (int h = 0; h < 2; h++) {
            int row = h ? row1 : row0;
            int j = h ? j1 : j0;
            uint32_t ad = as_b + ((((buf * 2 + 0) * 128 + row) * APAD + j * 4) << 2);
            cpa16(ad, Ahg + (size_t)(bm + row) * 256 + kw + j * 4);
            ad = as_b + ((((buf * 2 + 1) * 128 + row) * APAD + j * 4) << 2);
            cpa16(ad, Alg + (size_t)(bm + row) * 256 + kw + j * 4);
            uint32_t bd = bs_b + ((((buf * 2 + 0) * 128 + row) * APAD + j * 4) << 2);
            cpa16(bd, Bhg + (size_t)(bn + row) * 256 + kw + j * 4);
            bd = bs_b + ((((buf * 2 + 1) * 128 + row) * APAD + j * 4) << 2);
            cpa16(bd, Blg + (size_t)(bn + row) * 256 + kw + j * 4);
        }
    };

    load_tile(0, 0);
    asm volatile("cp.async.commit_group;");

    for (int kt = 0; kt < 16; kt++) {
        __syncthreads();   // everyone done computing buf[(kt+1)&1]
        if (kt < 15) load_tile(kt + 1, (kt + 1) & 1);
        asm volatile("cp.async.commit_group;");
        asm volatile("cp.async.wait_group 1;");
        __syncthreads();   // tile kt visible

        const int buf = kt & 1;
        const uint32_t* A0 = As + (buf * 2 + 0) * 128 * APAD;
        const uint32_t* A1 = As + (buf * 2 + 1) * 128 * APAD;
        const uint32_t* B0 = Bs + (buf * 2 + 0) * 128 * APAD;
        const uint32_t* B1 = Bs + (buf * 2 + 1) * 128 * APAD;

#pragma unroll
        for (int s = 0; s < 2; s++) {
            const int kb = s * 8 + (lane & 3);
            uint32_t ah[2][4], al[2][4];
#pragma unroll
            for (int mf = 0; mf < 2; mf++) {
                int r = wm + mf * 16 + (lane >> 2);
                ah[mf][0] = A0[r * APAD + kb];
                ah[mf][1] = A0[(r + 8) * APAD + kb];
                ah[mf][2] = A0[r * APAD + kb + 4];
                ah[mf][3] = A0[(r + 8) * APAD + kb + 4];
                al[mf][0] = A1[r * APAD + kb];
                al[mf][1] = A1[(r + 8) * APAD + kb];
                al[mf][2] = A1[r * APAD + kb + 4];
                al[mf][3] = A1[(r + 8) * APAD + kb + 4];
            }
#pragma unroll
            for (int nf = 0; nf < 8; nf++) {
                int n = wn + nf * 8 + (lane >> 2);
                uint32_t bh0 = B0[n * APAD + kb];
                uint32_t bh1 = B0[n * APAD + kb + 4];
                uint32_t bl0 = B1[n * APAD + kb];
                uint32_t bl1 = B1[n * APAD + kb + 4];
#pragma unroll
                for (int mf = 0; mf < 2; mf++) {
                    mma_bf16(acc[mf][nf], ah[mf], bh0, bh1);   // hi*hi
                    mma_bf16(acc[mf][nf], al[mf], bh0, bh1);   // lo*hi
                    mma_bf16(acc[mf][nf], ah[mf], bl0, bl1);   // hi*lo
                }
            }
        }
    }

    // epilogue: + bias, store
#pragma unroll
    for (int nf = 0; nf < 8; nf++) {
        int n = bn + wn + nf * 8 + 2 * (lane & 3);
        float2 bv = *(const float2*)(bias + n);
#pragma unroll
        for (int mf = 0; mf < 2; mf++) {
            int m = bm + wm + mf * 16 + (lane >> 2);
            float2 o0 = {acc[mf][nf][0] + bv.x, acc[mf][nf][1] + bv.y};
            float2 o1 = {acc[mf][nf][2] + bv.x, acc[mf][nf][3] + bv.y};
            *(float2*)(C + (size_t)m * 1536 + n) = o0;
            *(float2*)(C + (size_t)(m + 8) * 1536 + n) = o1;
        }
    }
}

// ============================================================================
// Phase 2 v2 (best known, R7): 256 CTAs = 8 bg x 32 ug, 2 CTAs/SM.
// ============================================================================
#define V2_NB 256

__global__ void __launch_bounds__(256, 2) gru_seq_v2(
    const float* __restrict__ xw,
    const float* __restrict__ rk,
    const float* __restrict__ bias,
    float* __restrict__ out,
    float* __restrict__ h0buf,
    float* __restrict__ h1buf,
    unsigned* __restrict__ ctr)
{
    __shared__ float hs[8 * 512];
    __shared__ float red[8 * 16 * 25];
    __shared__ float sbias[48];

    const int tid = threadIdx.x;
    const int bgid = blockIdx.x >> 5;
    const int ugid = blockIdx.x & 31;
    const int u0 = ugid * 16;
    const int b0 = bgid * 8;

    const int w = tid >> 5;
    const int lane = tid & 31;
    const int uu = lane & 15;
    const int kh = lane >> 4;
    const int kbase = w * 64 + kh * 32;

    ull Rz[16], Rr[16], Rh[16];
    {
        const float* rbase = rk + u0 + uu;
#pragma unroll
        for (int i = 0; i < 16; i++) {
            const float* r0 = rbase + (size_t)(kbase + 2 * i) * 1536;
            const float* r1 = r0 + 1536;
            Rz[i] = pack2(r0[0],    r1[0]);
            Rr[i] = pack2(r0[512],  r1[512]);
            Rh[i] = pack2(r0[1024], r1[1024]);
        }
    }
    if (tid < 48) {
        int u = tid / 3, g = tid - u * 3;
        sbias[u * 3 + g] = bias[1536 + g * 512 + u0 + u];
    }
    __syncthreads();

    const int eb = tid >> 4;
    const int eu = tid & 15;
    const float* xwp = xw + (size_t)(b0 + eb) * 1024 * 1536 + u0 + eu;
    float* outp = out + (size_t)(b0 + eb) * 524288 + u0 + eu;
    unsigned* myctr = ctr + bgid * 32;

    float hn_prev = 0.0f;

    for (int t = 0; t < 1024; t++) {
        float xz = 0.f, xr = 0.f, xh = 0.f;
        if (tid < 128) {
            const float* xr_ = xwp + (size_t)t * 1536;
            xz = __ldg(xr_);
            xr = __ldg(xr_ + 512);
            xh = __ldg(xr_ + 1024);
        }

        if (t > 0) {
            if (tid == 0) {
                unsigned target = (unsigned)(32 * t);
                unsigned v;
                do {
                    asm volatile("ld.acquire.gpu.global.u32 %0, [%1];"
                                 : "=r"(v) : "l"(myctr) : "memory");
                } while (v < target);
            }
            __syncthreads();
        }

        const float* hin = (t & 1) ? h1buf : h0buf;
        const float4* hsrc = (const float4*)(hin + b0 * 512);
#pragma unroll
        for (int i = 0; i < 4; i++) {
            int s = tid + i * 256;
            ((float4*)hs)[s] = __ldcg(hsrc + s);
        }
        __syncthreads();

#pragma unroll 1
        for (int b = 0; b < 8; b++) {
            ull az = 0ull, ar = 0ull, ah = 0ull;
            const float4* hp = (const float4*)(hs + b * 512 + kbase);
#pragma unroll
            for (int q = 0; q < 8; q++) {
                float4 h4 = hp[q];
                ull h01, h23;
                f4_to_u2(h4, h01, h23);
                fma2(az, h01, Rz[2 * q]); fma2(az, h23, Rz[2 * q + 1]);
                fma2(ar, h01, Rr[2 * q]); fma2(ar, h23, Rr[2 * q + 1]);
                fma2(ah, h01, Rh[2 * q]); fma2(ah, h23, Rh[2 * q + 1]);
            }
            float2 p;
            p = unpk(az); float vz = p.x + p.y;
            p = unpk(ar); float vr = p.x + p.y;
            p = unpk(ah); float vh = p.x + p.y;
            vz += __shfl_down_sync(0xffffffffu, vz, 16);
            vr += __shfl_down_sync(0xffffffffu, vr, 16);
            vh += __shfl_down_sync(0xffffffffu, vh, 16);
            if (kh == 0) {
                float* rb = red + (b * 16 + uu) * 25 + w * 3;
                rb[0] = vz; rb[1] = vr; rb[2] = vh;
            }
        }
        __syncthreads();

        float hn = 0.f;
        if (tid < 128) {
            float rz = sbias[eu * 3 + 0];
            float rr = sbias[eu * 3 + 1];
            float rh = sbias[eu * 3 + 2];
            const float* rb = red + (eb * 16 + eu) * 25;
#pragma unroll
            for (int s = 0; s < 8; s++) {
                rz += rb[s * 3 + 0];
                rr += rb[s * 3 + 1];
                rh += rb[s * 3 + 2];
            }
            float z  = sigf(xz + rz);
            float r  = sigf(xr + rr);
            float hh = tanh_acc(xh + r * rh);
            hn = z * hn_prev + (1.0f - z) * hh;
            hn_prev = hn;
            float* hout = (t & 1) ? h0buf : h1buf;
            __stcg(hout + (b0 + eb) * 512 + u0 + eu, hn);
        }
        __syncthreads();
        if (tid == 0) {
            asm volatile("red.release.gpu.global.add.u32 [%0], %1;"
                         :: "l"(myctr), "r"(1u) : "memory");
        }
        if (tid < 128) outp[(size_t)t * 512] = hn;
    }
}

// ============================================================================
// Phase 2 v1 (fallback): 128-CTA config.
// ============================================================================
#define NB2 128

__global__ void __launch_bounds__(256, 1) gru_seq_v1(
    const float* __restrict__ xw,
    const float* __restrict__ rk,
    const float* __restrict__ bias,
    float* __restrict__ out,
    float* __restrict__ h0buf,
    float* __restrict__ h1buf,
    unsigned* __restrict__ ctr)
{
    __shared__ float hs[8 * 512];
    __shared__ float red[256 * 25];

    const int tid = threadIdx.x;
    const int bgid = blockIdx.x >> 4;
    const int ugid = blockIdx.x & 15;
    const int u0 = ugid * 32;
    const int b0 = bgid * 8;

    const int w  = tid >> 5;
    const int uu = tid & 31;

    ull Rz[32], Rr[32], Rh[32];
    {
        const float* rbase = rk + u0 + uu;
#pragma unroll
        for (int i = 0; i < 32; i++) {
            int k = w * 64 + 2 * i;
            const float* r0 = rbase + (size_t)k * 1536;
            const float* r1 = r0 + 1536;
            Rz[i] = pack2(r0[0],    r1[0]);
            Rr[i] = pack2(r0[512],  r1[512]);
            Rh[i] = pack2(r0[1024], r1[1024]);
        }
    }
    const float bz  = bias[1536 + u0 + uu];
    const float brr = bias[1536 + 512 + u0 + uu];
    const float bh  = bias[1536 + 1024 + u0 + uu];

    const int bglob = b0 + w;
    const float* xwp = xw + (size_t)bglob * 1024 * 1536 + u0 + uu;
    float* outp = out + (size_t)bglob * 524288 + u0 + uu;
    unsigned* myctr = ctr + bgid * 32;

    float hn_prev = 0.0f;

    for (int t = 0; t < 1024; t++) {
        const float* xr_ = xwp + (size_t)t * 1536;
        float xz = __ldg(xr_);
        float xr = __ldg(xr_ + 512);
        float xh = __ldg(xr_ + 1024);

        const float* hin = (t & 1) ? h1buf : h0buf;
        if (t > 0) {
            if (tid == 0) {
                unsigned target = (unsigned)(16 * t);
                unsigned v;
                do {
                    asm volatile("ld.acquire.gpu.global.u32 %0, [%1];"
                                 : "=r"(v) : "l"(myctr) : "memory");
                } while (v < target);
            }
            __syncthreads();
        }
#pragma unroll
        for (int i = 0; i < 4; i++) {
            int s = i * 32 + uu;
            int b = s >> 4;
            int j4 = s & 15;
            float4 v = __ldcg((const float4*)(hin + (b0 + b) * 512 + w * 64) + j4);
            *(float4*)(hs + b * 512 + w * 64 + j4 * 4) = v;
        }
        __syncwarp();

#pragma unroll 1
        for (int b = 0; b < 8; b++) {
            ull az = 0ull, ar = 0ull, ah = 0ull;
            const float4* hp = (const float4*)(hs + b * 512 + w * 64);
#pragma unroll
            for (int q = 0; q < 16; q++) {
                float4 h4 = hp[q];
                ull h01, h23;
                f4_to_u2(h4, h01, h23);
                fma2(az, h01, Rz[2 * q]); fma2(az, h23, Rz[2 * q + 1]);
                fma2(ar, h01, Rr[2 * q]); fma2(ar, h23, Rr[2 * q + 1]);
                fma2(ah, h01, Rh[2 * q]); fma2(ah, h23, Rh[2 * q + 1]);
            }
            float2 pz = unpk(az), pr = unpk(ar), ph = unpk(ah);
            float* rb = red + (b * 32 + uu) * 25 + w * 3;
            rb[0] = pz.x + pz.y;
            rb[1] = pr.x + pr.y;
            rb[2] = ph.x + ph.y;
        }
        __syncthreads();

        float rz = bz, rr = brr, rh = bh;
        const float* rb = red + (w * 32 + uu) * 25;
#pragma unroll
        for (int s = 0; s < 8; s++) {
            rz += rb[s * 3 + 0];
            rr += rb[s * 3 + 1];
            rh += rb[s * 3 + 2];
        }
        float z  = sigf(xz + rz);
        float r  = sigf(xr + rr);
        float hh = tanh_acc(xh + r * rh);
        float hn = z * hn_prev + (1.0f - z) * hh;
        hn_prev = hn;

        float* hout = (t & 1) ? h0buf : h1buf;
        __stcg(hout + bglob * 512 + u0 + uu, hn);
        __threadfence();
        __syncthreads();
        if (tid == 0) atomicAdd(myctr, 1u);

        outp[(size_t)t * 512] = hn;
    }
}

// ============================================================================
extern "C" void kernel_launch(void* const* d_in, const int* in_sizes, int n_in,
                              void* d_out, int out_size) {
    const float* x    = (const float*)d_in[0];
    const float* W    = (const float*)d_in[1];
    const float* R    = (const float*)d_in[2];
    const float* bias = (const float*)d_in[3];
    float* out = (float*)d_out;

    float *xw_ptr, *h0_ptr, *h1_ptr;
    uint32_t *xh_ptr, *xl_ptr, *wh_ptr, *wl_ptr;
    unsigned* ctr_ptr;
    cudaGetSymbolAddress((void**)&xw_ptr, g_xw);
    cudaGetSymbolAddress((void**)&xh_ptr, g_xh);
    cudaGetSymbolAddress((void**)&xl_ptr, g_xl);
    cudaGetSymbolAddress((void**)&wh_ptr, g_wh);
    cudaGetSymbolAddress((void**)&wl_ptr, g_wl);
    cudaGetSymbolAddress((void**)&h0_ptr, g_h0);
    cudaGetSymbolAddress((void**)&h1_ptr, g_h1);
    cudaGetSymbolAddress((void**)&ctr_ptr, g_ctr);

    cudaMemsetAsync(h0_ptr, 0, 64 * 512 * sizeof(float));
    cudaMemsetAsync(ctr_ptr, 0, 8 * 32 * sizeof(unsigned));

    // ---- phase 1: convert + bf16x3 tensor GEMM ----
    conv_x_kernel<<<65536, 256>>>(x, xh_ptr, xl_ptr);
    conv_w_kernel<<<1536, 256>>>(W, wh_ptr, wl_ptr);

    const int smw_bytes = 2 * 2 * 2 * 128 * APAD * 4;   // 81920
    cudaFuncSetAttribute(gemm_xw_bf16x3,
                         cudaFuncAttributeMaxDynamicSharedMemorySize, smw_bytes);
    dim3 g1(12, 512);
    gemm_xw_bf16x3<<<g1, 256, smw_bytes>>>(xh_ptr, xl_ptr, wh_ptr, wl_ptr,
                                           bias, xw_ptr);

    // ---- phase 2: v2 if 2 CTAs/SM fit, else v1 ----
    int occ = 0;
    cudaError_t qe = cudaOccupancyMaxActiveBlocksPerMultiprocessor(
        &occ, gru_seq_v2, 256, 0);
    int nsm = 0;
    cudaDeviceGetAttribute(&nsm, cudaDevAttrMultiProcessorCount, 0);
    if (qe == cudaSuccess && occ >= 2 && nsm * 2 >= V2_NB) {
        gru_seq_v2<<<V2_NB, 256>>>(xw_ptr, R, bias, out, h0_ptr, h1_ptr, ctr_ptr);
    } else {
        (void)cudaGetLastError();
        gru_seq_v1<<<NB2, 256>>>(xw_ptr, R, bias, out, h0_ptr, h1_ptr, ctr_ptr);
    }
}

// round 10
// speedup vs baseline: 1.4357x; 1.1595x over previous
#include <cuda_runtime.h>
#include <cuda_bf16.h>
#include <cstdint>

typedef unsigned long long ull;

// ---------------- scratch (device globals: allocation-free) ----------------
__device__ float    g_xw[(size_t)64 * 1024 * 1536];   // 402 MB xw projections
__device__ uint32_t g_xh[(size_t)64 * 1024 * 256];    // x hi (bf16x2 pairs)
__device__ uint32_t g_xl[(size_t)64 * 1024 * 256];    // x lo
__device__ uint32_t g_wh[1536 * 256];                 // W^T hi
__device__ uint32_t g_wl[1536 * 256];                 // W^T lo
__device__ float    g_h0[64 * 512];
__device__ float    g_h1[64 * 512];
__device__ unsigned g_ctr[8 * 32];

// ---------------- helpers ----------------
__device__ __forceinline__ float sigf(float x) {
    return __fdividef(1.0f, 1.0f + __expf(-x));
}
__device__ __forceinline__ float tanh_acc(float x) {
    float ax = fabsf(x);
    float e = __expf(-2.0f * ax);
    float r = __fdividef(1.0f - e, 1.0f + e);
    return copysignf(r, x);
}
__device__ __forceinline__ uint32_t bf16pair(float even, float odd) {
    __nv_bfloat16 h0 = __float2bfloat16(even);
    __nv_bfloat16 h1 = __float2bfloat16(odd);
    return ((uint32_t)__bfloat16_as_ushort(h1) << 16) |
           (uint32_t)__bfloat16_as_ushort(h0);
}
__device__ __forceinline__ void split2(float x, float y,
                                       uint32_t& hi, uint32_t& lo) {
    __nv_bfloat16 hx = __float2bfloat16(x);
    __nv_bfloat16 hy = __float2bfloat16(y);
    hi = ((uint32_t)__bfloat16_as_ushort(hy) << 16) |
         (uint32_t)__bfloat16_as_ushort(hx);
    lo = bf16pair(x - __bfloat162float(hx), y - __bfloat162float(hy));
}

// ============================================================================
// Converters (phase 1 inputs)
// ============================================================================
__global__ void conv_x_kernel(const float* __restrict__ x,
                              uint32_t* __restrict__ xh,
                              uint32_t* __restrict__ xl) {
    size_t p = (size_t)blockIdx.x * 256 + threadIdx.x;
    float2 v = ((const float2*)x)[p];
    uint32_t hi, lo;
    split2(v.x, v.y, hi, lo);
    xh[p] = hi;
    xl[p] = lo;
}

__global__ void conv_w_kernel(const float* __restrict__ W,
                              uint32_t* __restrict__ wh,
                              uint32_t* __restrict__ wl) {
    int idx = blockIdx.x * 256 + threadIdx.x;
    int n = idx >> 8;
    int kp = idx & 255;
    float v0 = W[(size_t)(2 * kp) * 1536 + n];
    float v1 = W[(size_t)(2 * kp + 1) * 1536 + n];
    uint32_t hi, lo;
    split2(v0, v1, hi, lo);
    wh[idx] = hi;
    wl[idx] = lo;
}

// ============================================================================
// Phase 1: xw = x @ W + b_in via bf16x3 tensor mma (unchanged from R9)
// ============================================================================
#define APAD 20
#define KPT 16

__device__ __forceinline__ void cpa16(uint32_t saddr, const void* g) {
    asm volatile("cp.async.cg.shared.global [%0], [%1], 16;"
                 :: "r"(saddr), "l"(g));
}
__device__ __forceinline__ void mma_bf16(float* c, const uint32_t* a,
                                         uint32_t b0, uint32_t b1) {
    asm volatile(
        "mma.sync.aligned.m16n8k16.row.col.f32.bf16.bf16.f32 "
        "{%0,%1,%2,%3}, {%4,%5,%6,%7}, {%8,%9}, {%0,%1,%2,%3};"
        : "+f"(c[0]), "+f"(c[1]), "+f"(c[2]), "+f"(c[3])
        : "r"(a[0]), "r"(a[1]), "r"(a[2]), "r"(a[3]), "r"(b0), "r"(b1));
}

__global__ void __launch_bounds__(256, 2) gemm_xw_bf16x3(
    const uint32_t* __restrict__ Ahg,
    const uint32_t* __restrict__ Alg,
    const uint32_t* __restrict__ Bhg,
    const uint32_t* __restrict__ Blg,
    const float* __restrict__ bias,
    float* __restrict__ C)
{
    extern __shared__ uint32_t smw[];
    uint32_t* As = smw;
    uint32_t* Bs = smw + 2 * 2 * 128 * APAD;

    const int tid = threadIdx.x;
    const int lane = tid & 31;
    const int wid = tid >> 5;
    const int wm = (wid & 3) * 32;
    const int wn = (wid >> 2) * 64;
    const int bm = blockIdx.y * 128;
    const int bn = blockIdx.x * 128;

    const uint32_t as_b = (uint32_t)__cvta_generic_to_shared(As);
    const uint32_t bs_b = (uint32_t)__cvta_generic_to_shared(Bs);

    float acc[2][8][4];
#pragma unroll
    for (int mf = 0; mf < 2; mf++)
#pragma unroll
        for (int nf = 0; nf < 8; nf++)
#pragma unroll
            for (int i = 0; i < 4; i++) acc[mf][nf][i] = 0.0f;

    const int row0 = tid >> 2, j0 = (tid & 3);
    const int row1 = (tid + 256) >> 2, j1 = ((tid + 256) & 3);

    auto load_tile = [&](int kt, int buf) {
        int kw = kt * KPT;
#pragma unroll
        for (int h = 0; h < 2; h++) {
            int row = h ? row1 : row0;
            int j = h ? j1 : j0;
            uint32_t ad = as_b + ((((buf * 2 + 0) * 128 + row) * APAD + j * 4) << 2);
            cpa16(ad, Ahg + (size_t)(bm + row) * 256 + kw + j * 4);
            ad = as_b + ((((buf * 2 + 1) * 128 + row) * APAD + j * 4) << 2);
            cpa16(ad, Alg + (size_t)(bm + row) * 256 + kw + j * 4);
            uint32_t bd = bs_b + ((((buf * 2 + 0) * 128 + row) * APAD + j * 4) << 2);
            cpa16(bd, Bhg + (size_t)(bn + row) * 256 + kw + j * 4);
            bd = bs_b + ((((buf * 2 + 1) * 128 + row) * APAD + j * 4) << 2);
            cpa16(bd, Blg + (size_t)(bn + row) * 256 + kw + j * 4);
        }
    };

    load_tile(0, 0);
    asm volatile("cp.async.commit_group;");

    for (int kt = 0; kt < 16; kt++) {
        __syncthreads();
        if (kt < 15) load_tile(kt + 1, (kt + 1) & 1);
        asm volatile("cp.async.commit_group;");
        asm volatile("cp.async.wait_group 1;");
        __syncthreads();

        const int buf = kt & 1;
        const uint32_t* A0 = As + (buf * 2 + 0) * 128 * APAD;
        const uint32_t* A1 = As + (buf * 2 + 1) * 128 * APAD;
        const uint32_t* B0 = Bs + (buf * 2 + 0) * 128 * APAD;
        const uint32_t* B1 = Bs + (buf * 2 + 1) * 128 * APAD;

#pragma unroll
        for (int s = 0; s < 2; s++) {
            const int kb = s * 8 + (lane & 3);
            uint32_t ah[2][4], al[2][4];
#pragma unroll
            for (int mf = 0; mf < 2; mf++) {
                int r = wm + mf * 16 + (lane >> 2);
                ah[mf][0] = A0[r * APAD + kb];
                ah[mf][1] = A0[(r + 8) * APAD + kb];
                ah[mf][2] = A0[r * APAD + kb + 4];
                ah[mf][3] = A0[(r + 8) * APAD + kb + 4];
                al[mf][0] = A1[r * APAD + kb];
                al[mf][1] = A1[(r + 8) * APAD + kb];
                al[mf][2] = A1[r * APAD + kb + 4];
                al[mf][3] = A1[(r + 8) * APAD + kb + 4];
            }
#pragma unroll
            for (int nf = 0; nf < 8; nf++) {
                int n = wn + nf * 8 + (lane >> 2);
                uint32_t bh0 = B0[n * APAD + kb];
                uint32_t bh1 = B0[n * APAD + kb + 4];
                uint32_t bl0 = B1[n * APAD + kb];
                uint32_t bl1 = B1[n * APAD + kb + 4];
#pragma unroll
                for (int mf = 0; mf < 2; mf++) {
                    mma_bf16(acc[mf][nf], ah[mf], bh0, bh1);
                    mma_bf16(acc[mf][nf], al[mf], bh0, bh1);
                    mma_bf16(acc[mf][nf], ah[mf], bl0, bl1);
                }
            }
        }
    }

#pragma unroll
    for (int nf = 0; nf < 8; nf++) {
        int n = bn + wn + nf * 8 + 2 * (lane & 3);
        float2 bv = *(const float2*)(bias + n);
#pragma unroll
        for (int mf = 0; mf < 2; mf++) {
            int m = bm + wm + mf * 16 + (lane >> 2);
            float2 o0 = {acc[mf][nf][0] + bv.x, acc[mf][nf][1] + bv.y};
            float2 o1 = {acc[mf][nf][2] + bv.x, acc[mf][nf][3] + bv.y};
            *(float2*)(C + (size_t)m * 1536 + n) = o0;
            *(float2*)(C + (size_t)(m + 8) * 1536 + n) = o1;
        }
    }
}

// ============================================================================
// Phase 2 v4: v2 shape (256 CTAs = 8bg x 32ug, 2/SM) with the recurrent GEMM
//   on TENSOR CORES (bf16x3 m16n8k16). All 8 batches ride M (rows 8-15 zero).
//   Warp w owns k in [64w, 64w+64): 4 K-tiles x 2 n-tiles x 3 gates.
//   R-hi fragments in 48 regs/thread; R-lo streamed from smem; h split hi/lo
//   into smem during staging (stride 260 -> conflict-free fragment LDS).
// ============================================================================
#define V4_NB 256
// dynamic smem layout (uint32 words)
#define V4_RLO 0        // 12288
#define V4_HHI 12288    // 2080  (8 x 260)
#define V4_HLO 14368    // 2080
#define V4_RED 16448    // 3200 floats (128 x 25)
#define V4_SB  19648    // 48
#define V4_U32 19696
#define V4_BYTES (V4_U32 * 4)

__device__ __forceinline__ void mma8(float* c, uint32_t a0, uint32_t a2,
                                     uint32_t b0, uint32_t b1) {
    asm volatile(
        "mma.sync.aligned.m16n8k16.row.col.f32.bf16.bf16.f32 "
        "{%0,%1,%2,%3}, {%4,%5,%6,%7}, {%8,%9}, {%0,%1,%2,%3};"
        : "+f"(c[0]), "+f"(c[1]), "+f"(c[2]), "+f"(c[3])
        : "r"(a0), "r"(0u), "r"(a2), "r"(0u), "r"(b0), "r"(b1));
}

__global__ void __launch_bounds__(256, 2) gru_seq_v4(
    const float* __restrict__ xw,    // [65536, 1536]
    const float* __restrict__ rk,    // [512, 1536]
    const float* __restrict__ bias,  // [2, 1536] (row 1 = b_rec)
    float* __restrict__ out,         // [64, 1024, 512]
    float* __restrict__ h0buf,
    float* __restrict__ h1buf,
    unsigned* __restrict__ ctr)
{
    extern __shared__ uint32_t smv[];
    uint32_t* Rlo = smv + V4_RLO;
    uint32_t* hhi = smv + V4_HHI;
    uint32_t* hlo = smv + V4_HLO;
    float*    red = (float*)(smv + V4_RED);
    float*    sb  = (float*)(smv + V4_SB);

    const int tid = threadIdx.x;
    const int bgid = blockIdx.x >> 5;    // 0..7
    const int ugid = blockIdx.x & 31;    // 0..31
    const int u0 = ugid * 16;
    const int b0 = bgid * 8;

    const int w = tid >> 5;              // warp: k-chunk [64w, 64w+64)
    const int lane = tid & 31;

    // ---- preload R: hi fragments to regs, lo fragments to smem ----
    uint32_t Bh[48];
#pragma unroll
    for (int kt = 0; kt < 4; kt++)
#pragma unroll
        for (int nt = 0; nt < 2; nt++)
#pragma unroll
            for (int g = 0; g < 3; g++)
#pragma unroll
                for (int r = 0; r < 2; r++) {
                    int p = (w * 4 + kt) * 8 + (lane & 3) + r * 4;  // k-pair
                    int n = u0 + nt * 8 + (lane >> 2);
                    const float* q = rk + (size_t)(2 * p) * 1536 + g * 512 + n;
                    float v0 = q[0], v1 = q[1536];
                    uint32_t hi, lo;
                    split2(v0, v1, hi, lo);
                    Bh[((kt * 2 + nt) * 3 + g) * 2 + r] = hi;
                    Rlo[(((((w * 4 + kt) * 2 + nt) * 3 + g) * 2 + r)) * 32 + lane] = lo;
                }
    if (tid < 48) {
        int u = tid / 3, g = tid - u * 3;
        sb[u * 3 + g] = bias[1536 + g * 512 + u0 + u];
    }
    __syncthreads();

    // epilogue role (tid < 128): batch eb, unit eu
    const int eb = tid >> 4;
    const int eu = tid & 15;
    const float* xwp = xw + (size_t)(b0 + eb) * 1024 * 1536 + u0 + eu;
    float* outp = out + (size_t)(b0 + eb) * 524288 + u0 + eu;
    unsigned* myctr = ctr + bgid * 32;

    float hn_prev = 0.0f;

    for (int t = 0; t < 1024; t++) {
        // prefetch gate inputs (independent of h)
        float xz = 0.f, xr = 0.f, xh = 0.f;
        if (tid < 128) {
            const float* xr_ = xwp + (size_t)t * 1536;
            xz = __ldg(xr_);
            xr = __ldg(xr_ + 512);
            xh = __ldg(xr_ + 1024);
        }

        if (t > 0) {
            if (tid == 0) {
                unsigned target = (unsigned)(32 * t);
                unsigned v;
                do {
                    asm volatile("ld.acquire.gpu.global.u32 %0, [%1];"
                                 : "=r"(v) : "l"(myctr) : "memory");
                } while (v < target);
            }
            __syncthreads();
        }

        // ---- stage h + split to bf16 hi/lo: 1024 float4, 4 per thread ----
        const float* hin = (t & 1) ? h1buf : h0buf;
#pragma unroll
        for (int i = 0; i < 4; i++) {
            int s = tid + i * 256;
            int b = s >> 7, f4 = s & 127;
            float4 v = __ldcg((const float4*)(hin + (size_t)(b0 + b) * 512) + f4);
            uint32_t h01, l01, h23, l23;
            split2(v.x, v.y, h01, l01);
            split2(v.z, v.w, h23, l23);
            int a = b * 260 + 2 * f4;
            hhi[a] = h01; hhi[a + 1] = h23;
            hlo[a] = l01; hlo[a + 1] = l23;
        }
        __syncthreads();

        // ---- tensor GEMM partials: warp w, k in [64w, 64w+64) ----
        float accg[3][2][4];
#pragma unroll
        for (int g = 0; g < 3; g++)
#pragma unroll
            for (int nt = 0; nt < 2; nt++)
#pragma unroll
                for (int i = 0; i < 4; i++) accg[g][nt][i] = 0.0f;

#pragma unroll
        for (int kt = 0; kt < 4; kt++) {
            int pb = (w * 4 + kt) * 8 + (lane & 3);
            int ro = (lane >> 2) * 260;
            uint32_t a0h = hhi[ro + pb], a2h = hhi[ro + pb + 4];
            uint32_t a0l = hlo[ro + pb], a2l = hlo[ro + pb + 4];
#pragma unroll
            for (int g = 0; g < 3; g++)
#pragma unroll
                for (int nt = 0; nt < 2; nt++) {
                    uint32_t bh0 = Bh[((kt * 2 + nt) * 3 + g) * 2 + 0];
                    uint32_t bh1 = Bh[((kt * 2 + nt) * 3 + g) * 2 + 1];
                    mma8(accg[g][nt], a0h, a2h, bh0, bh1);
                    mma8(accg[g][nt], a0l, a2l, bh0, bh1);
                    uint32_t bl0 = Rlo[(((((w * 4 + kt) * 2 + nt) * 3 + g) * 2 + 0)) * 32 + lane];
                    uint32_t bl1 = Rlo[(((((w * 4 + kt) * 2 + nt) * 3 + g) * 2 + 1)) * 32 + lane];
                    mma8(accg[g][nt], a0h, a2h, bl0, bl1);
                }
        }

        // ---- write partials: thread = (batch lane>>2, units 2(lane&3)+) ----
        {
            int bb = lane >> 2, uc = 2 * (lane & 3);
#pragma unroll
            for (int g = 0; g < 3; g++)
#pragma unroll
                for (int nt = 0; nt < 2; nt++) {
                    int u = nt * 8 + uc;
                    red[(bb * 16 + u) * 25 + w * 3 + g]       = accg[g][nt][0];
                    red[(bb * 16 + u + 1) * 25 + w * 3 + g]   = accg[g][nt][1];
                }
        }
        __syncthreads();

        // ---- gates: tid<128, thread = (batch eb, unit eu) ----
        float hn = 0.f;
        if (tid < 128) {
            float rz = sb[eu * 3 + 0];
            float rr = sb[eu * 3 + 1];
            float rh = sb[eu * 3 + 2];
            const float* rb = red + (eb * 16 + eu) * 25;
#pragma unroll
            for (int s = 0; s < 8; s++) {
                rz += rb[s * 3 + 0];
                rr += rb[s * 3 + 1];
                rh += rb[s * 3 + 2];
            }
            float z  = sigf(xz + rz);
            float r  = sigf(xr + rr);
            float hh = tanh_acc(xh + r * rh);
            hn = z * hn_prev + (1.0f - z) * hh;
            hn_prev = hn;
            float* hout = (t & 1) ? h0buf : h1buf;
            __stcg(hout + (b0 + eb) * 512 + u0 + eu, hn);
        }
        __syncthreads();
        if (tid == 0) {
            asm volatile("red.release.gpu.global.add.u32 [%0], %1;"
                         :: "l"(myctr), "r"(1u) : "memory");
        }
        if (tid < 128) outp[(size_t)t * 512] = hn;
    }
}

// ============================================================================
extern "C" void kernel_launch(void* const* d_in, const int* in_sizes, int n_in,
                              void* d_out, int out_size) {
    const float* x    = (const float*)d_in[0];
    const float* W    = (const float*)d_in[1];
    const float* R    = (const float*)d_in[2];
    const float* bias = (const float*)d_in[3];
    float* out = (float*)d_out;

    float *xw_ptr, *h0_ptr, *h1_ptr;
    uint32_t *xh_ptr, *xl_ptr, *wh_ptr, *wl_ptr;
    unsigned* ctr_ptr;
    cudaGetSymbolAddress((void**)&xw_ptr, g_xw);
    cudaGetSymbolAddress((void**)&xh_ptr, g_xh);
    cudaGetSymbolAddress((void**)&xl_ptr, g_xl);
    cudaGetSymbolAddress((void**)&wh_ptr, g_wh);
    cudaGetSymbolAddress((void**)&wl_ptr, g_wl);
    cudaGetSymbolAddress((void**)&h0_ptr, g_h0);
    cudaGetSymbolAddress((void**)&h1_ptr, g_h1);
    cudaGetSymbolAddress((void**)&ctr_ptr, g_ctr);

    cudaMemsetAsync(h0_ptr, 0, 64 * 512 * sizeof(float));
    cudaMemsetAsync(ctr_ptr, 0, 8 * 32 * sizeof(unsigned));

    // ---- phase 1: convert + bf16x3 tensor GEMM ----
    conv_x_kernel<<<65536, 256>>>(x, xh_ptr, xl_ptr);
    conv_w_kernel<<<1536, 256>>>(W, wh_ptr, wl_ptr);

    const int smw_bytes = 2 * 2 * 2 * 128 * APAD * 4;
    cudaFuncSetAttribute(gemm_xw_bf16x3,
                         cudaFuncAttributeMaxDynamicSharedMemorySize, smw_bytes);
    dim3 g1(12, 512);
    gemm_xw_bf16x3<<<g1, 256, smw_bytes>>>(xh_ptr, xl_ptr, wh_ptr, wl_ptr,
                                           bias, xw_ptr);

    // ---- phase 2: tensor-core recurrence ----
    cudaFuncSetAttribute(gru_seq_v4,
                         cudaFuncAttributeMaxDynamicSharedMemorySize, V4_BYTES);
    gru_seq_v4<<<V4_NB, 256, V4_BYTES>>>(xw_ptr, R, bias, out,
                                         h0_ptr, h1_ptr, ctr_ptr);
}

// round 11
// speedup vs baseline: 1.5531x; 1.0818x over previous
#include <cuda_runtime.h>
#include <cuda_bf16.h>
#include <cstdint>

typedef unsigned long long ull;

// ---------------- scratch (device globals: allocation-free) ----------------
__device__ float    g_xw[(size_t)64 * 1024 * 1536];   // 402 MB xw projections
__device__ uint32_t g_xh[(size_t)64 * 1024 * 256];    // x hi (bf16x2 pairs)
__device__ uint32_t g_xl[(size_t)64 * 1024 * 256];    // x lo
__device__ uint32_t g_wh[1536 * 256];                 // W^T hi
__device__ uint32_t g_wl[1536 * 256];                 // W^T lo
__device__ float    g_h0[64 * 512];
__device__ float    g_h1[64 * 512];
__device__ unsigned g_ctr[8 * 32];

// ---------------- helpers ----------------
__device__ __forceinline__ float sigf(float x) {
    return __fdividef(1.0f, 1.0f + __expf(-x));
}
__device__ __forceinline__ float tanh_acc(float x) {
    float ax = fabsf(x);
    float e = __expf(-2.0f * ax);
    float r = __fdividef(1.0f - e, 1.0f + e);
    return copysignf(r, x);
}
__device__ __forceinline__ uint32_t bf16pair(float even, float odd) {
    __nv_bfloat16 h0 = __float2bfloat16(even);
    __nv_bfloat16 h1 = __float2bfloat16(odd);
    return ((uint32_t)__bfloat16_as_ushort(h1) << 16) |
           (uint32_t)__bfloat16_as_ushort(h0);
}
__device__ __forceinline__ void split2(float x, float y,
                                       uint32_t& hi, uint32_t& lo) {
    __nv_bfloat16 hx = __float2bfloat16(x);
    __nv_bfloat16 hy = __float2bfloat16(y);
    hi = ((uint32_t)__bfloat16_as_ushort(hy) << 16) |
         (uint32_t)__bfloat16_as_ushort(hx);
    lo = bf16pair(x - __bfloat162float(hx), y - __bfloat162float(hy));
}

// ============================================================================
// Converters (phase 1 inputs)
// ============================================================================
__global__ void conv_x_kernel(const float* __restrict__ x,
                              uint32_t* __restrict__ xh,
                              uint32_t* __restrict__ xl) {
    size_t p = (size_t)blockIdx.x * 256 + threadIdx.x;
    float2 v = ((const float2*)x)[p];
    uint32_t hi, lo;
    split2(v.x, v.y, hi, lo);
    xh[p] = hi;
    xl[p] = lo;
}

__global__ void conv_w_kernel(const float* __restrict__ W,
                              uint32_t* __restrict__ wh,
                              uint32_t* __restrict__ wl) {
    int idx = blockIdx.x * 256 + threadIdx.x;
    int n = idx >> 8;
    int kp = idx & 255;
    float v0 = W[(size_t)(2 * kp) * 1536 + n];
    float v1 = W[(size_t)(2 * kp + 1) * 1536 + n];
    uint32_t hi, lo;
    split2(v0, v1, hi, lo);
    wh[idx] = hi;
    wl[idx] = lo;
}

// ============================================================================
// Phase 1: xw = x @ W + b_in via bf16x3 tensor mma (unchanged from R9/R10)
// ============================================================================
#define APAD 20
#define KPT 16

__device__ __forceinline__ void cpa16(uint32_t saddr, const void* g) {
    asm volatile("cp.async.cg.shared.global [%0], [%1], 16;"
                 :: "r"(saddr), "l"(g));
}
__device__ __forceinline__ void mma_bf16(float* c, const uint32_t* a,
                                         uint32_t b0, uint32_t b1) {
    asm volatile(
        "mma.sync.aligned.m16n8k16.row.col.f32.bf16.bf16.f32 "
        "{%0,%1,%2,%3}, {%4,%5,%6,%7}, {%8,%9}, {%0,%1,%2,%3};"
        : "+f"(c[0]), "+f"(c[1]), "+f"(c[2]), "+f"(c[3])
        : "r"(a[0]), "r"(a[1]), "r"(a[2]), "r"(a[3]), "r"(b0), "r"(b1));
}

__global__ void __launch_bounds__(256, 2) gemm_xw_bf16x3(
    const uint32_t* __restrict__ Ahg,
    const uint32_t* __restrict__ Alg,
    const uint32_t* __restrict__ Bhg,
    const uint32_t* __restrict__ Blg,
    const float* __restrict__ bias,
    float* __restrict__ C)
{
    extern __shared__ uint32_t smw[];
    uint32_t* As = smw;
    uint32_t* Bs = smw + 2 * 2 * 128 * APAD;

    const int tid = threadIdx.x;
    const int lane = tid & 31;
    const int wid = tid >> 5;
    const int wm = (wid & 3) * 32;
    const int wn = (wid >> 2) * 64;
    const int bm = blockIdx.y * 128;
    const int bn = blockIdx.x * 128;

    const uint32_t as_b = (uint32_t)__cvta_generic_to_shared(As);
    const uint32_t bs_b = (uint32_t)__cvta_generic_to_shared(Bs);

    float acc[2][8][4];
#pragma unroll
    for (int mf = 0; mf < 2; mf++)
#pragma unroll
        for (int nf = 0; nf < 8; nf++)
#pragma unroll
            for (int i = 0; i < 4; i++) acc[mf][nf][i] = 0.0f;

    const int row0 = tid >> 2, j0 = (tid & 3);
    const int row1 = (tid + 256) >> 2, j1 = ((tid + 256) & 3);

    auto load_tile = [&](int kt, int buf) {
        int kw = kt * KPT;
#pragma unroll
        for (int h = 0; h < 2; h++) {
            int row = h ? row1 : row0;
            int j = h ? j1 : j0;
            uint32_t ad = as_b + ((((buf * 2 + 0) * 128 + row) * APAD + j * 4) << 2);
            cpa16(ad, Ahg + (size_t)(bm + row) * 256 + kw + j * 4);
            ad = as_b + ((((buf * 2 + 1) * 128 + row) * APAD + j * 4) << 2);
            cpa16(ad, Alg + (size_t)(bm + row) * 256 + kw + j * 4);
            uint32_t bd = bs_b + ((((buf * 2 + 0) * 128 + row) * APAD + j * 4) << 2);
            cpa16(bd, Bhg + (size_t)(bn + row) * 256 + kw + j * 4);
            bd = bs_b + ((((buf * 2 + 1) * 128 + row) * APAD + j * 4) << 2);
            cpa16(bd, Blg + (size_t)(bn + row) * 256 + kw + j * 4);
        }
    };

    load_tile(0, 0);
    asm volatile("cp.async.commit_group;");

    for (int kt = 0; kt < 16; kt++) {
        __syncthreads();
        if (kt < 15) load_tile(kt + 1, (kt + 1) & 1);
        asm volatile("cp.async.commit_group;");
        asm volatile("cp.async.wait_group 1;");
        __syncthreads();

        const int buf = kt & 1;
        const uint32_t* A0 = As + (buf * 2 + 0) * 128 * APAD;
        const uint32_t* A1 = As + (buf * 2 + 1) * 128 * APAD;
        const uint32_t* B0 = Bs + (buf * 2 + 0) * 128 * APAD;
        const uint32_t* B1 = Bs + (buf * 2 + 1) * 128 * APAD;

#pragma unroll
        for (int s = 0; s < 2; s++) {
            const int kb = s * 8 + (lane & 3);
            uint32_t ah[2][4], al[2][4];
#pragma unroll
            for (int mf = 0; mf < 2; mf++) {
                int r = wm + mf * 16 + (lane >> 2);
                ah[mf][0] = A0[r * APAD + kb];
                ah[mf][1] = A0[(r + 8) * APAD + kb];
                ah[mf][2] = A0[r * APAD + kb + 4];
                ah[mf][3] = A0[(r + 8) * APAD + kb + 4];
                al[mf][0] = A1[r * APAD + kb];
                al[mf][1] = A1[(r + 8) * APAD + kb];
                al[mf][2] = A1[r * APAD + kb + 4];
                al[mf][3] = A1[(r + 8) * APAD + kb + 4];
            }
#pragma unroll
            for (int nf = 0; nf < 8; nf++) {
                int n = wn + nf * 8 + (lane >> 2);
                uint32_t bh0 = B0[n * APAD + kb];
                uint32_t bh1 = B0[n * APAD + kb + 4];
                uint32_t bl0 = B1[n * APAD + kb];
                uint32_t bl1 = B1[n * APAD + kb + 4];
#pragma unroll
                for (int mf = 0; mf < 2; mf++) {
                    mma_bf16(acc[mf][nf], ah[mf], bh0, bh1);
                    mma_bf16(acc[mf][nf], al[mf], bh0, bh1);
                    mma_bf16(acc[mf][nf], ah[mf], bl0, bl1);
                }
            }
        }
    }

#pragma unroll
    for (int nf = 0; nf < 8; nf++) {
        int n = bn + wn + nf * 8 + 2 * (lane & 3);
        float2 bv = *(const float2*)(bias + n);
#pragma unroll
        for (int mf = 0; mf < 2; mf++) {
            int m = bm + wm + mf * 16 + (lane >> 2);
            float2 o0 = {acc[mf][nf][0] + bv.x, acc[mf][nf][1] + bv.y};
            float2 o1 = {acc[mf][nf][2] + bv.x, acc[mf][nf][3] + bv.y};
            *(float2*)(C + (size_t)m * 1536 + n) = o0;
            *(float2*)(C + (size_t)(m + 8) * 1536 + n) = o1;
        }
    }
}

// ============================================================================
// Phase 2 v5: v4 with SWAPPED mma operands — A = R^T (16 units on M, fully
//   used), B = h (8 batches on N=8, fully used). 36 mma/warp/step (was 72).
//   D[unit][batch]; R^T-hi fragments in 48 regs, R^T-lo streamed from smem,
//   h split hi/lo in smem (same staging/layout/sync as v4).
// ============================================================================
#define V5_NB 256
// dynamic smem layout (uint32 words)
#define V5_RLO 0        // 12288 (48 frag-regs x 32 lanes x 8 warps)
#define V5_HHI 12288    // 2080  (8 x 260)
#define V5_HLO 14368    // 2080
#define V5_RED 16448    // 3200 floats (128 x 25)
#define V5_SB  19648    // 48
#define V5_U32 19696
#define V5_BYTES (V5_U32 * 4)

__global__ void __launch_bounds__(256, 2) gru_seq_v5(
    const float* __restrict__ xw,    // [65536, 1536]
    const float* __restrict__ rk,    // [512, 1536]
    const float* __restrict__ bias,  // [2, 1536] (row 1 = b_rec)
    float* __restrict__ out,         // [64, 1024, 512]
    float* __restrict__ h0buf,
    float* __restrict__ h1buf,
    unsigned* __restrict__ ctr)
{
    extern __shared__ uint32_t smv[];
    uint32_t* Rlo = smv + V5_RLO;
    uint32_t* hhi = smv + V5_HHI;
    uint32_t* hlo = smv + V5_HLO;
    float*    red = (float*)(smv + V5_RED);
    float*    sb  = (float*)(smv + V5_SB);

    const int tid = threadIdx.x;
    const int bgid = blockIdx.x >> 5;    // 0..7
    const int ugid = blockIdx.x & 31;    // 0..31
    const int u0 = ugid * 16;
    const int b0 = bgid * 8;

    const int w = tid >> 5;              // warp: k-chunk [64w, 64w+64)
    const int lane = tid & 31;

    // ---- preload R^T A-fragments: hi to 48 regs, lo to smem ----
    // frag reg rr: unit = u0 + (lane>>2) + (rr&1)*8 ; k-pair = pb + (rr&2)*2
    uint32_t Ah[48];
#pragma unroll
    for (int kt = 0; kt < 4; kt++)
#pragma unroll
        for (int g = 0; g < 3; g++) {
            int pb = (w * 4 + kt) * 8 + (lane & 3);
            int urow = u0 + (lane >> 2);
#pragma unroll
            for (int rr = 0; rr < 4; rr++) {
                int un = urow + ((rr & 1) ? 8 : 0);
                int kp = pb + ((rr & 2) ? 4 : 0);
                const float* q = rk + (size_t)(2 * kp) * 1536 + g * 512 + un;
                float v0 = q[0], v1 = q[1536];
                uint32_t hi, lo;
                split2(v0, v1, hi, lo);
                Ah[(kt * 3 + g) * 4 + rr] = hi;
                Rlo[((((w * 4 + kt) * 3 + g) * 4 + rr)) * 32 + lane] = lo;
            }
        }
    if (tid < 48) {
        int u = tid / 3, g = tid - u * 3;
        sb[u * 3 + g] = bias[1536 + g * 512 + u0 + u];
    }
    __syncthreads();

    // epilogue role (tid < 128): batch eb, unit eu (coalesced unit-contig)
    const int eb = tid >> 4;
    const int eu = tid & 15;
    const float* xwp = xw + (size_t)(b0 + eb) * 1024 * 1536 + u0 + eu;
    float* outp = out + (size_t)(b0 + eb) * 524288 + u0 + eu;
    unsigned* myctr = ctr + bgid * 32;

    float hn_prev = 0.0f;

    for (int t = 0; t < 1024; t++) {
        // prefetch gate inputs (independent of h)
        float xz = 0.f, xr = 0.f, xh = 0.f;
        if (tid < 128) {
            const float* xr_ = xwp + (size_t)t * 1536;
            xz = __ldg(xr_);
            xr = __ldg(xr_ + 512);
            xh = __ldg(xr_ + 1024);
        }

        if (t > 0) {
            if (tid == 0) {
                unsigned target = (unsigned)(32 * t);
                unsigned v;
                do {
                    asm volatile("ld.acquire.gpu.global.u32 %0, [%1];"
                                 : "=r"(v) : "l"(myctr) : "memory");
                } while (v < target);
            }
            __syncthreads();
        }

        // ---- stage h + split to bf16 hi/lo: 1024 float4, 4 per thread ----
        const float* hin = (t & 1) ? h1buf : h0buf;
#pragma unroll
        for (int i = 0; i < 4; i++) {
            int s = tid + i * 256;
            int b = s >> 7, f4 = s & 127;
            float4 v = __ldcg((const float4*)(hin + (size_t)(b0 + b) * 512) + f4);
            uint32_t h01, l01, h23, l23;
            split2(v.x, v.y, h01, l01);
            split2(v.z, v.w, h23, l23);
            int a = b * 260 + 2 * f4;
            hhi[a] = h01; hhi[a + 1] = h23;
            hlo[a] = l01; hlo[a + 1] = l23;
        }
        __syncthreads();

        // ---- tensor GEMM partials: warp w, k in [64w, 64w+64) ----
        // A = R^T (units on M), B = h (batches on N) -> 36 mma/warp
        float accg[3][4];
#pragma unroll
        for (int g = 0; g < 3; g++)
#pragma unroll
            for (int i = 0; i < 4; i++) accg[g][i] = 0.0f;

#pragma unroll
        for (int kt = 0; kt < 4; kt++) {
            int pb = (w * 4 + kt) * 8 + (lane & 3);
            int bo = (lane >> 2) * 260;            // batch = lane>>2
            uint32_t b0h = hhi[bo + pb], b1h = hhi[bo + pb + 4];
            uint32_t b0l = hlo[bo + pb], b1l = hlo[bo + pb + 4];
#pragma unroll
            for (int g = 0; g < 3; g++) {
                const uint32_t* A = Ah + (kt * 3 + g) * 4;
                mma_bf16(accg[g], A, b0h, b1h);     // R_hi * h_hi
                mma_bf16(accg[g], A, b0l, b1l);     // R_hi * h_lo
                uint32_t al[4];
#pragma unroll
                for (int rr = 0; rr < 4; rr++)
                    al[rr] = Rlo[((((w * 4 + kt) * 3 + g) * 4 + rr)) * 32 + lane];
                mma_bf16(accg[g], al, b0h, b1h);    // R_lo * h_hi
            }
        }

        // ---- write partials: c -> D[unit row][batch col] ----
        {
            int row = lane >> 2;              // unit (low 8)
            int col = 2 * (lane & 3);         // batch
#pragma unroll
            for (int g = 0; g < 3; g++) {
                red[((col    ) * 16 + row    ) * 25 + w * 3 + g] = accg[g][0];
                red[((col + 1) * 16 + row    ) * 25 + w * 3 + g] = accg[g][1];
                red[((col    ) * 16 + row + 8) * 25 + w * 3 + g] = accg[g][2];
                red[((col + 1) * 16 + row + 8) * 25 + w * 3 + g] = accg[g][3];
            }
        }
        __syncthreads();

        // ---- gates: tid<128, thread = (batch eb, unit eu) ----
        float hn = 0.f;
        if (tid < 128) {
            float rz = sb[eu * 3 + 0];
            float rr = sb[eu * 3 + 1];
            float rh = sb[eu * 3 + 2];
            const float* rb = red + (eb * 16 + eu) * 25;
#pragma unroll
            for (int s = 0; s < 8; s++) {
                rz += rb[s * 3 + 0];
                rr += rb[s * 3 + 1];
                rh += rb[s * 3 + 2];
            }
            float z  = sigf(xz + rz);
            float r  = sigf(xr + rr);
            float hh = tanh_acc(xh + r * rh);
            hn = z * hn_prev + (1.0f - z) * hh;
            hn_prev = hn;
            float* hout = (t & 1) ? h0buf : h1buf;
            __stcg(hout + (b0 + eb) * 512 + u0 + eu, hn);
        }
        __syncthreads();
        if (tid == 0) {
            asm volatile("red.release.gpu.global.add.u32 [%0], %1;"
                         :: "l"(myctr), "r"(1u) : "memory");
        }
        if (tid < 128) outp[(size_t)t * 512] = hn;
    }
}

// ============================================================================
extern "C" void kernel_launch(void* const* d_in, const int* in_sizes, int n_in,
                              void* d_out, int out_size) {
    const float* x    = (const float*)d_in[0];
    const float* W    = (const float*)d_in[1];
    const float* R    = (const float*)d_in[2];
    const float* bias = (const float*)d_in[3];
    float* out = (float*)d_out;

    float *xw_ptr, *h0_ptr, *h1_ptr;
    uint32_t *xh_ptr, *xl_ptr, *wh_ptr, *wl_ptr;
    unsigned* ctr_ptr;
    cudaGetSymbolAddress((void**)&xw_ptr, g_xw);
    cudaGetSymbolAddress((void**)&xh_ptr, g_xh);
    cudaGetSymbolAddress((void**)&xl_ptr, g_xl);
    cudaGetSymbolAddress((void**)&wh_ptr, g_wh);
    cudaGetSymbolAddress((void**)&wl_ptr, g_wl);
    cudaGetSymbolAddress((void**)&h0_ptr, g_h0);
    cudaGetSymbolAddress((void**)&h1_ptr, g_h1);
    cudaGetSymbolAddress((void**)&ctr_ptr, g_ctr);

    cudaMemsetAsync(h0_ptr, 0, 64 * 512 * sizeof(float));
    cudaMemsetAsync(ctr_ptr, 0, 8 * 32 * sizeof(unsigned));

    // ---- phase 1: convert + bf16x3 tensor GEMM ----
    conv_x_kernel<<<65536, 256>>>(x, xh_ptr, xl_ptr);
    conv_w_kernel<<<1536, 256>>>(W, wh_ptr, wl_ptr);

    const int smw_bytes = 2 * 2 * 2 * 128 * APAD * 4;
    cudaFuncSetAttribute(gemm_xw_bf16x3,
                         cudaFuncAttributeMaxDynamicSharedMemorySize, smw_bytes);
    dim3 g1(12, 512);
    gemm_xw_bf16x3<<<g1, 256, smw_bytes>>>(xh_ptr, xl_ptr, wh_ptr, wl_ptr,
                                           bias, xw_ptr);

    // ---- phase 2: tensor-core recurrence, operand-swapped ----
    cudaFuncSetAttribute(gru_seq_v5,
                         cudaFuncAttributeMaxDynamicSharedMemorySize, V5_BYTES);
    gru_seq_v5<<<V5_NB, 256, V5_BYTES>>>(xw_ptr, R, bias, out,
                                         h0_ptr, h1_ptr, ctr_ptr);
}